// round 2
// baseline (speedup 1.0000x reference)
#include <cuda_runtime.h>
#include <math.h>

#define NMAX  100000
#define FIN   128
#define C1    16
#define C2    8

// Scratch (device globals: allocation-free per harness rules)
__device__ float g_deg [NMAX];
__device__ float g_dinv[NMAX];
__device__ float g_hw1 [NMAX * C1];
__device__ float g_h1  [NMAX * C1];
__device__ float g_hw2 [NMAX * C2];
__device__ float g_h2  [NMAX * C2];
__device__ float g_z   [NMAX];

// ---------------------------------------------------------------------------
// K0: init deg=1 (self loop), h1 = b1 broadcast, h2 = b2 broadcast
__global__ void k_init(const float* __restrict__ b1,
                       const float* __restrict__ b2, int n) {
    int t = blockIdx.x * blockDim.x + threadIdx.x;
    if (t < n * C1) g_h1[t] = b1[t & (C1 - 1)];
    if (t < n * C2) g_h2[t] = b2[t & (C2 - 1)];
    if (t < n)      g_deg[t] = 1.0f;
}

// K1: degree scatter over E edges (dst row of edge_index)
__global__ void k_deg(const int* __restrict__ dst, int E) {
    int e = blockIdx.x * blockDim.x + threadIdx.x;
    if (e < E) atomicAdd(&g_deg[dst[e]], 1.0f);
}

// K2: dinv = rsqrt(deg)   (deg >= 1 always, self loop)
__global__ void k_dinv(int n) {
    int i = blockIdx.x * blockDim.x + threadIdx.x;
    if (i < n) g_dinv[i] = rsqrtf(g_deg[i]);
}

// K3: hw1 = x @ W1 ; h1 += dinv^2 * hw1 (self-loop term; h1 already = b1)
__global__ void k_gemm1(const float* __restrict__ x,
                        const float* __restrict__ W1, int n) {
    __shared__ float Ws[FIN * C1];  // 8KB
    for (int t = threadIdx.x; t < FIN * C1; t += blockDim.x)
        Ws[t] = W1[t];
    __syncthreads();
    int i = blockIdx.x * blockDim.x + threadIdx.x;
    if (i >= n) return;
    float acc[C1];
#pragma unroll
    for (int c = 0; c < C1; c++) acc[c] = 0.0f;
    const float4* x4 = reinterpret_cast<const float4*>(x + (size_t)i * FIN);
#pragma unroll 8
    for (int k4 = 0; k4 < FIN / 4; k4++) {
        float4 v = x4[k4];
        const float* w0 = &Ws[(k4 * 4 + 0) * C1];
        const float* w1 = &Ws[(k4 * 4 + 1) * C1];
        const float* w2 = &Ws[(k4 * 4 + 2) * C1];
        const float* w3 = &Ws[(k4 * 4 + 3) * C1];
#pragma unroll
        for (int c = 0; c < C1; c++)
            acc[c] += v.x * w0[c] + v.y * w1[c] + v.z * w2[c] + v.w * w3[c];
    }
    float dv = g_dinv[i];
    float w  = dv * dv;
#pragma unroll
    for (int c = 0; c < C1; c++) {
        g_hw1[i * C1 + c] = acc[c];
        g_h1 [i * C1 + c] += w * acc[c];
    }
}

// K4: edge scatter layer 1 — 16 lanes per edge, coalesced REDs
__global__ void k_scat1(const int* __restrict__ src,
                        const int* __restrict__ dst, int E) {
    long long gt = (long long)blockIdx.x * blockDim.x + threadIdx.x;
    int e = (int)(gt >> 4);
    int c = (int)(gt & 15);
    if (e >= E) return;
    int s = src[e];
    int d = dst[e];
    float w = g_dinv[s] * g_dinv[d];
    atomicAdd(&g_h1[d * C1 + c], w * g_hw1[s * C1 + c]);
}

// K5: hw2 = h1 @ W2 ; h2 += dinv^2 * hw2
__global__ void k_gemm2(const float* __restrict__ W2, int n) {
    __shared__ float Ws[C1 * C2];  // 128 floats
    for (int t = threadIdx.x; t < C1 * C2; t += blockDim.x)
        Ws[t] = W2[t];
    __syncthreads();
    int i = blockIdx.x * blockDim.x + threadIdx.x;
    if (i >= n) return;
    float acc[C2];
#pragma unroll
    for (int c = 0; c < C2; c++) acc[c] = 0.0f;
#pragma unroll
    for (int k = 0; k < C1; k++) {
        float v = g_h1[i * C1 + k];
#pragma unroll
        for (int c = 0; c < C2; c++) acc[c] += v * Ws[k * C2 + c];
    }
    float dv = g_dinv[i];
    float w  = dv * dv;
#pragma unroll
    for (int c = 0; c < C2; c++) {
        g_hw2[i * C2 + c] = acc[c];
        g_h2 [i * C2 + c] += w * acc[c];
    }
}

// K6: edge scatter layer 2 — 8 lanes per edge
__global__ void k_scat2(const int* __restrict__ src,
                        const int* __restrict__ dst, int E) {
    long long gt = (long long)blockIdx.x * blockDim.x + threadIdx.x;
    int e = (int)(gt >> 3);
    int c = (int)(gt & 7);
    if (e >= E) return;
    int s = src[e];
    int d = dst[e];
    float w = g_dinv[s] * g_dinv[d];
    atomicAdd(&g_h2[d * C2 + c], w * g_hw2[s * C2 + c]);
}

// K7: z = sigmoid(h2 @ Wl + bl)
__global__ void k_head(const float* __restrict__ Wl,
                       const float* __restrict__ bl, int n) {
    int i = blockIdx.x * blockDim.x + threadIdx.x;
    if (i >= n) return;
    float acc = bl[0];
#pragma unroll
    for (int c = 0; c < C2; c++) acc += g_h2[i * C2 + c] * Wl[c];
    g_z[i] = 1.0f / (1.0f + expf(-acc));
}

// K8: pred[p] = z[pe[p,0]] * z[pe[p,1]]
__global__ void k_pred(const int* __restrict__ pe,
                       float* __restrict__ out, int P) {
    int p = blockIdx.x * blockDim.x + threadIdx.x;
    if (p >= P) return;
    int2 ab = reinterpret_cast<const int2*>(pe)[p];
    out[p] = g_z[ab.x] * g_z[ab.y];
}

extern "C" void kernel_launch(void* const* d_in, const int* in_sizes, int n_in,
                              void* d_out, int out_size) {
    const float* x   = (const float*)d_in[0];
    const int*   ei  = (const int*)d_in[1];
    const int*   pe  = (const int*)d_in[2];
    const float* W1  = (const float*)d_in[3];
    const float* b1  = (const float*)d_in[4];
    const float* W2  = (const float*)d_in[5];
    const float* b2  = (const float*)d_in[6];
    const float* Wl  = (const float*)d_in[7];
    const float* bl  = (const float*)d_in[8];
    float* out = (float*)d_out;

    int n = in_sizes[0] / FIN;
    int E = in_sizes[1] / 2;
    int P = in_sizes[2] / 2;

    const int* src = ei;
    const int* dst = ei + E;

    const int T = 256;

    k_init<<<(n * C1 + T - 1) / T, T>>>(b1, b2, n);
    k_deg <<<(E + T - 1) / T, T>>>(dst, E);
    k_dinv<<<(n + T - 1) / T, T>>>(n);
    k_gemm1<<<(n + 127) / 128, 128>>>(x, W1, n);
    {
        long long tot = (long long)E * C1;
        k_scat1<<<(unsigned)((tot + T - 1) / T), T>>>(src, dst, E);
    }
    k_gemm2<<<(n + T - 1) / T, T>>>(W2, n);
    {
        long long tot = (long long)E * C2;
        k_scat2<<<(unsigned)((tot + T - 1) / T), T>>>(src, dst, E);
    }
    k_head<<<(n + T - 1) / T, T>>>(Wl, bl, n);
    k_pred<<<(P + T - 1) / T, T>>>(pe, out, P);
}